// round 2
// baseline (speedup 1.0000x reference)
#include <cuda_runtime.h>
#include <cstdint>
#include <math.h>

#define NS 8192
#define NE 8192
#define HH 512
#define PP 64

// Scratch for normalized projections (allocation-free: __device__ globals).
__device__ float g_sub_proj[NS * PP];
__device__ float g_edge_proj[NE * PP];

// ---------------------------------------------------------------------------
// proj = l2_normalize(X @ W^T + b), X:[N,512], W:[64,512], out:[N,64]
// One warp computes 2 rows. W rows read as float4 (L1/L2-hot, 128KB total).
// ---------------------------------------------------------------------------
__global__ __launch_bounds__(256) void proj_kernel(const float* __restrict__ X,
                                                   const float* __restrict__ W,
                                                   const float* __restrict__ b,
                                                   int which)
{
    float* out = which ? g_edge_proj : g_sub_proj;
    const int warp = threadIdx.x >> 5;
    const int lane = threadIdx.x & 31;
    const int r0 = blockIdx.x * 16 + warp * 2;

    const float4* X4 = reinterpret_cast<const float4*>(X);
    const float4* W4 = reinterpret_cast<const float4*>(W);

    float4 xa[4], xb[4];
#pragma unroll
    for (int j = 0; j < 4; j++) {
        xa[j] = X4[(size_t)r0 * 128 + lane + 32 * j];
        xb[j] = X4[(size_t)(r0 + 1) * 128 + lane + 32 * j];
    }

    float ya0 = 0.f, ya1 = 0.f, yb0 = 0.f, yb1 = 0.f;
    for (int p = 0; p < 64; p++) {
        float sa = 0.f, sb = 0.f;
#pragma unroll
        for (int j = 0; j < 4; j++) {
            float4 w = W4[p * 128 + lane + 32 * j];
            sa = fmaf(xa[j].x, w.x, sa); sa = fmaf(xa[j].y, w.y, sa);
            sa = fmaf(xa[j].z, w.z, sa); sa = fmaf(xa[j].w, w.w, sa);
            sb = fmaf(xb[j].x, w.x, sb); sb = fmaf(xb[j].y, w.y, sb);
            sb = fmaf(xb[j].z, w.z, sb); sb = fmaf(xb[j].w, w.w, sb);
        }
#pragma unroll
        for (int off = 16; off > 0; off >>= 1) {
            sa += __shfl_xor_sync(0xffffffffu, sa, off);
            sb += __shfl_xor_sync(0xffffffffu, sb, off);
        }
        if ((p & 31) == lane) {
            if (p < 32) { ya0 = sa; yb0 = sb; }
            else        { ya1 = sa; yb1 = sb; }
        }
    }
    ya0 += b[lane];      yb0 += b[lane];
    ya1 += b[lane + 32]; yb1 += b[lane + 32];

    float na = ya0 * ya0 + ya1 * ya1;
    float nb = yb0 * yb0 + yb1 * yb1;
#pragma unroll
    for (int off = 16; off > 0; off >>= 1) {
        na += __shfl_xor_sync(0xffffffffu, na, off);
        nb += __shfl_xor_sync(0xffffffffu, nb, off);
    }
    float inva = 1.0f / fmaxf(sqrtf(na), 1e-12f);
    float invb = 1.0f / fmaxf(sqrtf(nb), 1e-12f);

    out[(size_t)r0 * 64 + lane]            = ya0 * inva;
    out[(size_t)r0 * 64 + 32 + lane]       = ya1 * inva;
    out[(size_t)(r0 + 1) * 64 + lane]      = yb0 * invb;
    out[(size_t)(r0 + 1) * 64 + 32 + lane] = yb1 * invb;
}

// ---------------------------------------------------------------------------
// scores GEMM: out[s,e] = (sub_proj[s,:] . edge_proj[e,:]) * scale * 0.5
// 128x128 tile per block, 8x8 per thread, K=64 in two 32-wide smem chunks.
// Tiles stored k-major (As[k][row]) for conflict-free LDS.128.
// ---------------------------------------------------------------------------
__global__ __launch_bounds__(256) void scores_kernel(const float* __restrict__ log_scale,
                                                     float* __restrict__ out)
{
    __shared__ float As[32][128];
    __shared__ float Bs[32][128];

    const int tid  = threadIdx.x;
    const int brow = blockIdx.y * 128;
    const int bcol = blockIdx.x * 128;
    const int tx = tid & 15;
    const int ty = tid >> 4;

    const float4* A4 = reinterpret_cast<const float4*>(g_sub_proj);
    const float4* B4 = reinterpret_cast<const float4*>(g_edge_proj);

    float acc[8][8];
#pragma unroll
    for (int i = 0; i < 8; i++)
#pragma unroll
        for (int j = 0; j < 8; j++) acc[i][j] = 0.f;

#pragma unroll
    for (int kb = 0; kb < 2; kb++) {
        if (kb) __syncthreads();
#pragma unroll
        for (int it = 0; it < 4; it++) {
            int idx = tid + it * 256;      // 0..1023
            int r   = idx & 127;
            int pk  = idx >> 7;            // 0..7 (float4 within 32-wide chunk)
            float4 va = A4[(size_t)(brow + r) * 16 + kb * 8 + pk];
            As[4 * pk + 0][r] = va.x; As[4 * pk + 1][r] = va.y;
            As[4 * pk + 2][r] = va.z; As[4 * pk + 3][r] = va.w;
            float4 vb = B4[(size_t)(bcol + r) * 16 + kb * 8 + pk];
            Bs[4 * pk + 0][r] = vb.x; Bs[4 * pk + 1][r] = vb.y;
            Bs[4 * pk + 2][r] = vb.z; Bs[4 * pk + 3][r] = vb.w;
        }
        __syncthreads();
#pragma unroll
        for (int k = 0; k < 32; k++) {
            float a[8], bb[8];
            *reinterpret_cast<float4*>(&a[0])  = *reinterpret_cast<const float4*>(&As[k][ty * 8]);
            *reinterpret_cast<float4*>(&a[4])  = *reinterpret_cast<const float4*>(&As[k][ty * 8 + 4]);
            *reinterpret_cast<float4*>(&bb[0]) = *reinterpret_cast<const float4*>(&Bs[k][tx * 8]);
            *reinterpret_cast<float4*>(&bb[4]) = *reinterpret_cast<const float4*>(&Bs[k][tx * 8 + 4]);
#pragma unroll
            for (int i = 0; i < 8; i++)
#pragma unroll
                for (int j = 0; j < 8; j++)
                    acc[i][j] = fmaf(a[i], bb[j], acc[i][j]);
        }
    }

    const float zs = 0.5f * fminf(fmaxf(expf(*log_scale), 0.5f), 20.0f);

#pragma unroll
    for (int i = 0; i < 8; i++) {
        size_t o = (size_t)(brow + ty * 8 + i) * NE + bcol + tx * 8;
        float4 o0 = make_float4(acc[i][0] * zs, acc[i][1] * zs, acc[i][2] * zs, acc[i][3] * zs);
        float4 o1 = make_float4(acc[i][4] * zs, acc[i][5] * zs, acc[i][6] * zs, acc[i][7] * zs);
        *reinterpret_cast<float4*>(out + o)     = o0;
        *reinterpret_cast<float4*>(out + o + 4) = o1;
    }
}

// ---------------------------------------------------------------------------
// entmax-1.5 per row, in place. tau* is the unique root of
//   g(tau) = sqrt(sum relu(z-tau)^2) = 1   on [zmax-1, zmax)
// g is convex decreasing -> Newton from the left bracket is monotone and
// quadratically convergent; on the final support this is exactly the
// reference's closed-form tau_star. p = relu(z - tau)^2.
// ---------------------------------------------------------------------------
__global__ __launch_bounds__(256) void entmax_kernel(float* __restrict__ out)
{
    __shared__ float s1s[8], s2s[8];
    __shared__ float sb0, sb1;

    const int tid  = threadIdx.x;
    const int lane = tid & 31;
    const int warp = tid >> 5;
    float4* row = reinterpret_cast<float4*>(out + (size_t)blockIdx.x * NE);

    float4 v[8];
#pragma unroll
    for (int j = 0; j < 8; j++) v[j] = row[tid + 256 * j];

    // row max
    float m = -3.4e38f;
#pragma unroll
    for (int j = 0; j < 8; j++)
        m = fmaxf(m, fmaxf(fmaxf(v[j].x, v[j].y), fmaxf(v[j].z, v[j].w)));
#pragma unroll
    for (int off = 16; off > 0; off >>= 1)
        m = fmaxf(m, __shfl_xor_sync(0xffffffffu, m, off));
    if (lane == 0) s1s[warp] = m;
    __syncthreads();
    if (tid == 0) {
        float mm = s1s[0];
#pragma unroll
        for (int w = 1; w < 8; w++) mm = fmaxf(mm, s1s[w]);
        sb0 = mm;
    }
    __syncthreads();

    float tau = sb0 - 1.0f;

    for (int it = 0; it < 64; it++) {
        float a = 0.f, q = 0.f;
#pragma unroll
        for (int j = 0; j < 8; j++) {
            float d;
            d = fmaxf(v[j].x - tau, 0.f); a += d; q = fmaf(d, d, q);
            d = fmaxf(v[j].y - tau, 0.f); a += d; q = fmaf(d, d, q);
            d = fmaxf(v[j].z - tau, 0.f); a += d; q = fmaf(d, d, q);
            d = fmaxf(v[j].w - tau, 0.f); a += d; q = fmaf(d, d, q);
        }
#pragma unroll
        for (int off = 16; off > 0; off >>= 1) {
            a += __shfl_xor_sync(0xffffffffu, a, off);
            q += __shfl_xor_sync(0xffffffffu, q, off);
        }
        if (lane == 0) { s1s[warp] = a; s2s[warp] = q; }
        __syncthreads();
        if (tid == 0) {
            float A = 0.f, Q = 0.f;
#pragma unroll
            for (int w = 0; w < 8; w++) { A += s1s[w]; Q += s2s[w]; }
            sb0 = A; sb1 = Q;
        }
        __syncthreads();
        float S1 = sb0;
        float S2 = sb1;
        if (S1 <= 0.f) break;
        float g  = sqrtf(S2);
        float dt = (S2 - g) / S1;   // Newton on g(tau)-1
        tau += dt;
        if (fabsf(dt) < 1e-7f) break;
    }

#pragma unroll
    for (int j = 0; j < 8; j++) {
        float4 o;
        float d;
        d = fmaxf(v[j].x - tau, 0.f); o.x = d * d;
        d = fmaxf(v[j].y - tau, 0.f); o.y = d * d;
        d = fmaxf(v[j].z - tau, 0.f); o.z = d * d;
        d = fmaxf(v[j].w - tau, 0.f); o.w = d * d;
        row[tid + 256 * j] = o;
    }
}

// ---------------------------------------------------------------------------
extern "C" void kernel_launch(void* const* d_in, const int* in_sizes, int n_in,
                              void* d_out, int out_size)
{
    const float* edge_repr = (const float*)d_in[0];
    const float* sub_repr  = (const float*)d_in[1];
    const float* W_sub     = (const float*)d_in[2];
    const float* b_sub     = (const float*)d_in[3];
    const float* W_edge    = (const float*)d_in[4];
    const float* b_edge    = (const float*)d_in[5];
    const float* log_scale = (const float*)d_in[6];
    float* out = (float*)d_out;

    proj_kernel<<<NS / 16, 256>>>(sub_repr,  W_sub,  b_sub,  0);
    proj_kernel<<<NE / 16, 256>>>(edge_repr, W_edge, b_edge, 1);

    dim3 grid(NE / 128, NS / 128);
    scores_kernel<<<grid, 256>>>(log_scale, out);

    entmax_kernel<<<NS, 256>>>(out);
}

// round 4
// speedup vs baseline: 1.2155x; 1.2155x over previous
#include <cuda_runtime.h>
#include <cuda_bf16.h>
#include <cstdint>
#include <math.h>

#define NS 8192
#define NE 8192
#define HH 512
#define PP 64
#define KC 192              // concatenated K = 3 * 64 (hi,hi,lo / hi,lo,hi)

// bf16 split operands: [N, 192] row-major.
__device__ __nv_bfloat16 g_sub_cat[(size_t)NS * KC];
__device__ __nv_bfloat16 g_edge_cat[(size_t)NE * KC];

__device__ __forceinline__ uint32_t smem_u32(const void* p) {
    uint32_t a;
    asm("{ .reg .u64 t; cvta.to.shared.u64 t, %1; cvt.u32.u64 %0, t; }" : "=r"(a) : "l"(p));
    return a;
}

__device__ __forceinline__ void ldmx4(uint32_t* r, uint32_t addr) {
    asm volatile("ldmatrix.sync.aligned.m8n8.x4.shared.b16 {%0,%1,%2,%3}, [%4];"
                 : "=r"(r[0]), "=r"(r[1]), "=r"(r[2]), "=r"(r[3]) : "r"(addr));
}

__device__ __forceinline__ void mma16816(float* d, const uint32_t* a, const uint32_t* b) {
    asm volatile(
        "mma.sync.aligned.m16n8k16.row.col.f32.bf16.bf16.f32 "
        "{%0,%1,%2,%3}, {%4,%5,%6,%7}, {%8,%9}, {%0,%1,%2,%3};"
        : "+f"(d[0]), "+f"(d[1]), "+f"(d[2]), "+f"(d[3])
        : "r"(a[0]), "r"(a[1]), "r"(a[2]), "r"(a[3]), "r"(b[0]), "r"(b[1]));
}

// ---------------------------------------------------------------------------
// proj: y = l2_normalize(X @ W^T + b); writes bf16 hi/lo concat [N,192].
// which=0 (sub):  [hi, hi, lo].   which=1 (edge): [hi, lo, hi].
// ---------------------------------------------------------------------------
__global__ __launch_bounds__(256) void proj_kernel(const float* __restrict__ X,
                                                   const float* __restrict__ W,
                                                   const float* __restrict__ b,
                                                   int which)
{
    __nv_bfloat16* out = which ? g_edge_cat : g_sub_cat;
    const int warp = threadIdx.x >> 5;
    const int lane = threadIdx.x & 31;
    const int r0 = blockIdx.x * 16 + warp * 2;

    const float4* X4 = reinterpret_cast<const float4*>(X);
    const float4* W4 = reinterpret_cast<const float4*>(W);

    float4 xa[4], xb[4];
#pragma unroll
    for (int j = 0; j < 4; j++) {
        xa[j] = X4[(size_t)r0 * 128 + lane + 32 * j];
        xb[j] = X4[(size_t)(r0 + 1) * 128 + lane + 32 * j];
    }

    float ya0 = 0.f, ya1 = 0.f, yb0 = 0.f, yb1 = 0.f;
    for (int p = 0; p < 64; p++) {
        float sa = 0.f, sb = 0.f;
#pragma unroll
        for (int j = 0; j < 4; j++) {
            float4 w = W4[p * 128 + lane + 32 * j];
            sa = fmaf(xa[j].x, w.x, sa); sa = fmaf(xa[j].y, w.y, sa);
            sa = fmaf(xa[j].z, w.z, sa); sa = fmaf(xa[j].w, w.w, sa);
            sb = fmaf(xb[j].x, w.x, sb); sb = fmaf(xb[j].y, w.y, sb);
            sb = fmaf(xb[j].z, w.z, sb); sb = fmaf(xb[j].w, w.w, sb);
        }
#pragma unroll
        for (int off = 16; off > 0; off >>= 1) {
            sa += __shfl_xor_sync(0xffffffffu, sa, off);
            sb += __shfl_xor_sync(0xffffffffu, sb, off);
        }
        if ((p & 31) == lane) {
            if (p < 32) { ya0 = sa; yb0 = sb; }
            else        { ya1 = sa; yb1 = sb; }
        }
    }
    ya0 += b[lane];      yb0 += b[lane];
    ya1 += b[lane + 32]; yb1 += b[lane + 32];

    float na = ya0 * ya0 + ya1 * ya1;
    float nb = yb0 * yb0 + yb1 * yb1;
#pragma unroll
    for (int off = 16; off > 0; off >>= 1) {
        na += __shfl_xor_sync(0xffffffffu, na, off);
        nb += __shfl_xor_sync(0xffffffffu, nb, off);
    }
    float inva = 1.0f / fmaxf(sqrtf(na), 1e-12f);
    float invb = 1.0f / fmaxf(sqrtf(nb), 1e-12f);

    float va[2] = { ya0 * inva, ya1 * inva };
    float vb[2] = { yb0 * invb, yb1 * invb };

#pragma unroll
    for (int h = 0; h < 2; h++) {
        int p = lane + 32 * h;
        {
            float v = va[h];
            __nv_bfloat16 hi = __float2bfloat16(v);
            __nv_bfloat16 lo = __float2bfloat16(v - __bfloat162float(hi));
            size_t base = (size_t)r0 * KC;
            out[base + p] = hi;
            if (which == 0) { out[base + 64 + p] = hi; out[base + 128 + p] = lo; }
            else            { out[base + 64 + p] = lo; out[base + 128 + p] = hi; }
        }
        {
            float v = vb[h];
            __nv_bfloat16 hi = __float2bfloat16(v);
            __nv_bfloat16 lo = __float2bfloat16(v - __bfloat162float(hi));
            size_t base = (size_t)(r0 + 1) * KC;
            out[base + p] = hi;
            if (which == 0) { out[base + 64 + p] = hi; out[base + 128 + p] = lo; }
            else            { out[base + 64 + p] = lo; out[base + 128 + p] = hi; }
        }
    }
}

// ---------------------------------------------------------------------------
// scores GEMM via mma.sync (HMMA bf16): 128x128 tile/CTA, K=192 from smem.
// 8 warps, each 32(M)x64(N). smem rows padded to 400B (conflict-free ldmatrix).
// ---------------------------------------------------------------------------
#define PITCH_B 400                    // bytes per smem row (192*2=384 used)
#define SMEM_SC (2 * 128 * PITCH_B)    // 102400 bytes

__global__ __launch_bounds__(256) void scores_mma_kernel(const float* __restrict__ log_scale,
                                                         float* __restrict__ out)
{
    extern __shared__ char smem[];
    const uint32_t sA = smem_u32(smem);
    const uint32_t sB = sA + 128 * PITCH_B;

    const int tid  = threadIdx.x;
    const int wid  = tid >> 5;
    const int lane = tid & 31;
    const int wm = wid & 3;        // 4 warps along M
    const int wn = wid >> 2;       // 2 warps along N
    const int brow = blockIdx.y * 128;
    const int bcol = blockIdx.x * 128;

    // ---- load A/B tiles to smem (128 rows x 24 uint4 each)
    const uint4* A4 = reinterpret_cast<const uint4*>(g_sub_cat);
    const uint4* B4 = reinterpret_cast<const uint4*>(g_edge_cat);
#pragma unroll
    for (int it = 0; it < 12; it++) {
        int i  = tid + it * 256;       // 0..3071
        int r  = i / 24;
        int ch = i - r * 24;
        uint4 va = A4[(size_t)(brow + r) * 24 + ch];
        *reinterpret_cast<uint4*>(smem + r * PITCH_B + ch * 16) = va;
        uint4 vb = B4[(size_t)(bcol + r) * 24 + ch];
        *reinterpret_cast<uint4*>(smem + 128 * PITCH_B + r * PITCH_B + ch * 16) = vb;
    }
    __syncthreads();

    float acc[2][8][4];
#pragma unroll
    for (int mt = 0; mt < 2; mt++)
#pragma unroll
        for (int nt = 0; nt < 8; nt++)
#pragma unroll
            for (int q = 0; q < 4; q++) acc[mt][nt][q] = 0.f;

    const int g = lane >> 3;
    const int rl = lane & 7;

    // precomputed row-part addresses
    //  A tiles: row = wm*32 + mt*16 + rl + (g&1)*8 ; col = kb + (g>>1)*8
    uint32_t aRow[2];
#pragma unroll
    for (int mt = 0; mt < 2; mt++)
        aRow[mt] = sA + (wm * 32 + mt * 16 + rl + (g & 1) * 8) * PITCH_B + ((g >> 1) * 8) * 2;
    //  B pairs: rows n0 + rl + (g>>1)*8 ; col = kb + (g&1)*8
    uint32_t bRow[4];
#pragma unroll
    for (int pn = 0; pn < 4; pn++)
        bRow[pn] = sB + (wn * 64 + pn * 16 + rl + (g >> 1) * 8) * PITCH_B + ((g & 1) * 8) * 2;

#pragma unroll
    for (int k = 0; k < 12; k++) {
        const uint32_t kb = k * 32;    // 16 bf16 = 32 bytes
        uint32_t af[2][4], bf[4][4];
#pragma unroll
        for (int mt = 0; mt < 2; mt++) ldmx4(af[mt], aRow[mt] + kb);
#pragma unroll
        for (int pn = 0; pn < 4; pn++) ldmx4(bf[pn], bRow[pn] + kb);
#pragma unroll
        for (int mt = 0; mt < 2; mt++)
#pragma unroll
            for (int pn = 0; pn < 4; pn++) {
                mma16816(acc[mt][2 * pn],     af[mt], &bf[pn][0]);
                mma16816(acc[mt][2 * pn + 1], af[mt], &bf[pn][2]);
            }
    }

    const float zs = 0.5f * fminf(fmaxf(expf(*log_scale), 0.5f), 20.0f);

    // epilogue: direct float2 stores (32B-contiguous per row across 4 lanes)
    const int r0 = brow + wm * 32 + (lane >> 2);
    const int c0 = bcol + wn * 64 + 2 * (lane & 3);
#pragma unroll
    for (int mt = 0; mt < 2; mt++)
#pragma unroll
        for (int nt = 0; nt < 8; nt++) {
            float* p0 = out + (size_t)(r0 + mt * 16) * NE + c0 + nt * 8;
            float* p1 = p0 + 8 * NE;
            *reinterpret_cast<float2*>(p0) =
                make_float2(acc[mt][nt][0] * zs, acc[mt][nt][1] * zs);
            *reinterpret_cast<float2*>(p1) =
                make_float2(acc[mt][nt][2] * zs, acc[mt][nt][3] * zs);
        }
}

// ---------------------------------------------------------------------------
// entmax-1.5 per row, in place. Newton on g(tau)=sqrt(sum relu(z-tau)^2)=1,
// monotone from tau = zmax - 1. 512 threads/row, 1 barrier per iteration
// (double-buffered partials + broadcast-read final sum).
// ---------------------------------------------------------------------------
__global__ __launch_bounds__(512) void entmax_kernel(float* __restrict__ out)
{
    __shared__ float s1[2][16], s2[2][16], smax[16];

    const int tid  = threadIdx.x;
    const int lane = tid & 31;
    const int warp = tid >> 5;
    float4* row = reinterpret_cast<float4*>(out + (size_t)blockIdx.x * NE);

    float4 v[4];
#pragma unroll
    for (int j = 0; j < 4; j++) v[j] = row[tid + 512 * j];

    float m = -3.4e38f;
#pragma unroll
    for (int j = 0; j < 4; j++)
        m = fmaxf(m, fmaxf(fmaxf(v[j].x, v[j].y), fmaxf(v[j].z, v[j].w)));
#pragma unroll
    for (int off = 16; off > 0; off >>= 1)
        m = fmaxf(m, __shfl_xor_sync(0xffffffffu, m, off));
    if (lane == 0) smax[warp] = m;
    __syncthreads();
    float mm = smax[0];
#pragma unroll
    for (int w = 1; w < 16; w++) mm = fmaxf(mm, smax[w]);

    float tau = mm - 1.0f;

#pragma unroll 1
    for (int it = 0; it < 32; it++) {
        const int p = it & 1;
        float a = 0.f, q = 0.f;
#pragma unroll
        for (int j = 0; j < 4; j++) {
            float d;
            d = fmaxf(v[j].x - tau, 0.f); a += d; q = fmaf(d, d, q);
            d = fmaxf(v[j].y - tau, 0.f); a += d; q = fmaf(d, d, q);
            d = fmaxf(v[j].z - tau, 0.f); a += d; q = fmaf(d, d, q);
            d = fmaxf(v[j].w - tau, 0.f); a += d; q = fmaf(d, d, q);
        }
#pragma unroll
        for (int off = 16; off > 0; off >>= 1) {
            a += __shfl_xor_sync(0xffffffffu, a, off);
            q += __shfl_xor_sync(0xffffffffu, q, off);
        }
        if (lane == 0) { s1[p][warp] = a; s2[p][warp] = q; }
        __syncthreads();
        float S1 = 0.f, S2 = 0.f;
#pragma unroll
        for (int w = 0; w < 16; w++) { S1 += s1[p][w]; S2 += s2[p][w]; }
        if (S1 <= 0.f) break;
        float gg = sqrtf(S2);
        float dt = (S2 - gg) / S1;    // Newton step on g(tau)-1
        tau += dt;
        if (fabsf(dt) < 1e-7f) break;
    }

#pragma unroll
    for (int j = 0; j < 4; j++) {
        float4 o;
        float d;
        d = fmaxf(v[j].x - tau, 0.f); o.x = d * d;
        d = fmaxf(v[j].y - tau, 0.f); o.y = d * d;
        d = fmaxf(v[j].z - tau, 0.f); o.z = d * d;
        d = fmaxf(v[j].w - tau, 0.f); o.w = d * d;
        row[tid + 512 * j] = o;
    }
}

// ---------------------------------------------------------------------------
extern "C" void kernel_launch(void* const* d_in, const int* in_sizes, int n_in,
                              void* d_out, int out_size)
{
    const float* edge_repr = (const float*)d_in[0];
    const float* sub_repr  = (const float*)d_in[1];
    const float* W_sub     = (const float*)d_in[2];
    const float* b_sub     = (const float*)d_in[3];
    const float* W_edge    = (const float*)d_in[4];
    const float* b_edge    = (const float*)d_in[5];
    const float* log_scale = (const float*)d_in[6];
    float* out = (float*)d_out;

    cudaFuncSetAttribute(scores_mma_kernel,
                         cudaFuncAttributeMaxDynamicSharedMemorySize, SMEM_SC);

    proj_kernel<<<NS / 16, 256>>>(sub_repr,  W_sub,  b_sub,  0);
    proj_kernel<<<NE / 16, 256>>>(edge_repr, W_edge, b_edge, 1);

    dim3 grid(NE / 128, NS / 128);
    scores_mma_kernel<<<grid, 256, SMEM_SC>>>(log_scale, out);

    entmax_kernel<<<NS, 512>>>(out);
}

// round 5
// speedup vs baseline: 1.4236x; 1.1712x over previous
#include <cuda_runtime.h>
#include <cuda_bf16.h>
#include <cstdint>
#include <math.h>

#define NS 8192
#define NE 8192
#define HH 512
#define PP 64
#define KC 192              // concatenated K = 3 * 64 (hi,hi,lo / hi,lo,hi)

// bf16 split operands: [N, 192] row-major.
__device__ __nv_bfloat16 g_sub_cat[(size_t)NS * KC];
__device__ __nv_bfloat16 g_edge_cat[(size_t)NE * KC];

__device__ __forceinline__ uint32_t smem_u32(const void* p) {
    uint32_t a;
    asm("{ .reg .u64 t; cvta.to.shared.u64 t, %1; cvt.u32.u64 %0, t; }" : "=r"(a) : "l"(p));
    return a;
}
__device__ __forceinline__ void ldmx4(uint32_t* r, uint32_t addr) {
    asm volatile("ldmatrix.sync.aligned.m8n8.x4.shared.b16 {%0,%1,%2,%3}, [%4];"
                 : "=r"(r[0]), "=r"(r[1]), "=r"(r[2]), "=r"(r[3]) : "r"(addr));
}
__device__ __forceinline__ void mma16816(float* d, const uint32_t* a, const uint32_t* b) {
    asm volatile(
        "mma.sync.aligned.m16n8k16.row.col.f32.bf16.bf16.f32 "
        "{%0,%1,%2,%3}, {%4,%5,%6,%7}, {%8,%9}, {%0,%1,%2,%3};"
        : "+f"(d[0]), "+f"(d[1]), "+f"(d[2]), "+f"(d[3])
        : "r"(a[0]), "r"(a[1]), "r"(a[2]), "r"(a[3]), "r"(b[0]), "r"(b[1]));
}
__device__ __forceinline__ void cpa16(uint32_t s, const void* g) {
    asm volatile("cp.async.cg.shared.global [%0], [%1], 16;" :: "r"(s), "l"(g) : "memory");
}

// ---------------------------------------------------------------------------
// proj: y = l2_normalize(X @ W^T + b); writes bf16 hi/lo concat [N,192].
// which=0 (sub):  [hi, hi, lo].   which=1 (edge): [hi, lo, hi].
// ---------------------------------------------------------------------------
__global__ __launch_bounds__(256) void proj_kernel(const float* __restrict__ X,
                                                   const float* __restrict__ W,
                                                   const float* __restrict__ b,
                                                   int which)
{
    __nv_bfloat16* out = which ? g_edge_cat : g_sub_cat;
    const int warp = threadIdx.x >> 5;
    const int lane = threadIdx.x & 31;
    const int r0 = blockIdx.x * 16 + warp * 2;

    const float4* X4 = reinterpret_cast<const float4*>(X);
    const float4* W4 = reinterpret_cast<const float4*>(W);

    float4 xa[4], xb[4];
#pragma unroll
    for (int j = 0; j < 4; j++) {
        xa[j] = X4[(size_t)r0 * 128 + lane + 32 * j];
        xb[j] = X4[(size_t)(r0 + 1) * 128 + lane + 32 * j];
    }

    float ya0 = 0.f, ya1 = 0.f, yb0 = 0.f, yb1 = 0.f;
    for (int p = 0; p < 64; p++) {
        float sa = 0.f, sb = 0.f;
#pragma unroll
        for (int j = 0; j < 4; j++) {
            float4 w = W4[p * 128 + lane + 32 * j];
            sa = fmaf(xa[j].x, w.x, sa); sa = fmaf(xa[j].y, w.y, sa);
            sa = fmaf(xa[j].z, w.z, sa); sa = fmaf(xa[j].w, w.w, sa);
            sb = fmaf(xb[j].x, w.x, sb); sb = fmaf(xb[j].y, w.y, sb);
            sb = fmaf(xb[j].z, w.z, sb); sb = fmaf(xb[j].w, w.w, sb);
        }
#pragma unroll
        for (int off = 16; off > 0; off >>= 1) {
            sa += __shfl_xor_sync(0xffffffffu, sa, off);
            sb += __shfl_xor_sync(0xffffffffu, sb, off);
        }
        if ((p & 31) == lane) {
            if (p < 32) { ya0 = sa; yb0 = sb; }
            else        { ya1 = sa; yb1 = sb; }
        }
    }
    ya0 += b[lane];      yb0 += b[lane];
    ya1 += b[lane + 32]; yb1 += b[lane + 32];

    float na = ya0 * ya0 + ya1 * ya1;
    float nb = yb0 * yb0 + yb1 * yb1;
#pragma unroll
    for (int off = 16; off > 0; off >>= 1) {
        na += __shfl_xor_sync(0xffffffffu, na, off);
        nb += __shfl_xor_sync(0xffffffffu, nb, off);
    }
    float inva = 1.0f / fmaxf(sqrtf(na), 1e-12f);
    float invb = 1.0f / fmaxf(sqrtf(nb), 1e-12f);

    float va[2] = { ya0 * inva, ya1 * inva };
    float vb[2] = { yb0 * invb, yb1 * invb };

#pragma unroll
    for (int h = 0; h < 2; h++) {
        int p = lane + 32 * h;
        {
            float v = va[h];
            __nv_bfloat16 hi = __float2bfloat16(v);
            __nv_bfloat16 lo = __float2bfloat16(v - __bfloat162float(hi));
            size_t base = (size_t)r0 * KC;
            out[base + p] = hi;
            if (which == 0) { out[base + 64 + p] = hi; out[base + 128 + p] = lo; }
            else            { out[base + 64 + p] = lo; out[base + 128 + p] = hi; }
        }
        {
            float v = vb[h];
            __nv_bfloat16 hi = __float2bfloat16(v);
            __nv_bfloat16 lo = __float2bfloat16(v - __bfloat162float(hi));
            size_t base = (size_t)(r0 + 1) * KC;
            out[base + p] = hi;
            if (which == 0) { out[base + 64 + p] = hi; out[base + 128 + p] = lo; }
            else            { out[base + 64 + p] = lo; out[base + 128 + p] = hi; }
        }
    }
}

// ---------------------------------------------------------------------------
// scores GEMM via mma.sync: 128x128 tile/CTA, K=192 in 3 chunks of 64,
// cp.async double-buffered, XOR-swizzled smem (conflict-free ldmatrix).
// smem: buf b at b*32KB: A chunk 16KB (128 rows x 128B), B chunk at +16KB.
// ---------------------------------------------------------------------------
#define SMEM_SC 65536

__global__ __launch_bounds__(256) void scores_mma_kernel(const float* __restrict__ log_scale,
                                                         float* __restrict__ out)
{
    extern __shared__ char smem[];
    const uint32_t sbase = smem_u32(smem);

    const int tid  = threadIdx.x;
    const int wid  = tid >> 5;
    const int lane = tid & 31;
    const int wm = wid & 3;        // 4 warps along M
    const int wn = wid >> 2;       // 2 warps along N
    const int brow = blockIdx.y * 128;
    const int bcol = blockIdx.x * 128;

    const char* gA = reinterpret_cast<const char*>(g_sub_cat);
    const char* gB = reinterpret_cast<const char*>(g_edge_cat);

    // per-thread load slots: 4 (row, quad) pairs per operand per chunk
    const int lr0 = tid >> 3;       // rows lr0 + 32j
    const int lq  = tid & 7;        // 16B quad within 128B row-chunk

    auto load_chunk = [&](int c, int b) {
        const uint32_t bufA = sbase + (uint32_t)b * 32768u;
        const uint32_t bufB = bufA + 16384u;
#pragma unroll
        for (int j = 0; j < 4; j++) {
            int r = lr0 + 32 * j;
            uint32_t d = (uint32_t)r * 128u + (uint32_t)((lq ^ (r & 7)) << 4);
            cpa16(bufA + d, gA + (size_t)(brow + r) * 384 + c * 128 + lq * 16);
            cpa16(bufB + d, gB + (size_t)(bcol + r) * 384 + c * 128 + lq * 16);
        }
        asm volatile("cp.async.commit_group;" ::: "memory");
    };

    float acc[2][8][4];
#pragma unroll
    for (int mt = 0; mt < 2; mt++)
#pragma unroll
        for (int nt = 0; nt < 8; nt++)
#pragma unroll
            for (int q = 0; q < 4; q++) acc[mt][nt][q] = 0.f;

    const int g  = lane >> 3;
    const int rl = lane & 7;
    const int gl = g & 1;
    const int gh = g >> 1;

    // fragment row offsets (bytes) within a chunk buffer; row&7 == rl always
    uint32_t aOff[2], bOff[4];
#pragma unroll
    for (int mt = 0; mt < 2; mt++)
        aOff[mt] = (uint32_t)(wm * 32 + mt * 16 + rl + gl * 8) * 128u;
#pragma unroll
    for (int pn = 0; pn < 4; pn++)
        bOff[pn] = (uint32_t)(wn * 64 + pn * 16 + rl + gh * 8) * 128u;

    load_chunk(0, 0);

#pragma unroll
    for (int c = 0; c < 3; c++) {
        if (c == 0) {
            load_chunk(1, 1);
            asm volatile("cp.async.wait_group 1;" ::: "memory");
        } else if (c == 1) {
            load_chunk(2, 0);
            asm volatile("cp.async.wait_group 1;" ::: "memory");
        } else {
            asm volatile("cp.async.wait_group 0;" ::: "memory");
        }
        __syncthreads();

        const uint32_t bufA = sbase + (uint32_t)(c & 1) * 32768u;
        const uint32_t bufB = bufA + 16384u;

#pragma unroll
        for (int s = 0; s < 4; s++) {
            const uint32_t ca = (uint32_t)(((2 * s + gh) ^ rl) << 4);
            const uint32_t cb = (uint32_t)(((2 * s + gl) ^ rl) << 4);
            uint32_t af[2][4], bf[4][4];
#pragma unroll
            for (int mt = 0; mt < 2; mt++) ldmx4(af[mt], bufA + aOff[mt] + ca);
#pragma unroll
            for (int pn = 0; pn < 4; pn++) ldmx4(bf[pn], bufB + bOff[pn] + cb);
#pragma unroll
            for (int mt = 0; mt < 2; mt++)
#pragma unroll
                for (int pn = 0; pn < 4; pn++) {
                    mma16816(acc[mt][2 * pn],     af[mt], &bf[pn][0]);
                    mma16816(acc[mt][2 * pn + 1], af[mt], &bf[pn][2]);
                }
        }
        if (c < 2) __syncthreads();
    }

    const float zs = 0.5f * fminf(fmaxf(expf(*log_scale), 0.5f), 20.0f);

    const int r0 = brow + wm * 32 + (lane >> 2);
    const int c0 = bcol + wn * 64 + 2 * (lane & 3);
#pragma unroll
    for (int mt = 0; mt < 2; mt++)
#pragma unroll
        for (int nt = 0; nt < 8; nt++) {
            float* p0 = out + (size_t)(r0 + mt * 16) * NE + c0 + nt * 8;
            float* p1 = p0 + 8 * NE;
            *reinterpret_cast<float2*>(p0) =
                make_float2(acc[mt][nt][0] * zs, acc[mt][nt][1] * zs);
            *reinterpret_cast<float2*>(p1) =
                make_float2(acc[mt][nt][2] * zs, acc[mt][nt][3] * zs);
        }
}

// ---------------------------------------------------------------------------
// entmax-1.5 per row, in place. Newton on g(tau)=sqrt(sum relu(z-tau)^2)=1,
// monotone from tau = zmax-1. 256 threads/row, 32 elems in regs,
// single barrier per iter (double-buffered partials, 8-wide broadcast sum).
// ---------------------------------------------------------------------------
__global__ __launch_bounds__(256) void entmax_kernel(float* __restrict__ out)
{
    __shared__ float s1[2][8], s2[2][8], smax[8];

    const int tid  = threadIdx.x;
    const int lane = tid & 31;
    const int warp = tid >> 5;
    float4* row = reinterpret_cast<float4*>(out + (size_t)blockIdx.x * NE);

    float4 v[8];
#pragma unroll
    for (int j = 0; j < 8; j++) v[j] = row[tid + 256 * j];

    float m = -3.4e38f;
#pragma unroll
    for (int j = 0; j < 8; j++)
        m = fmaxf(m, fmaxf(fmaxf(v[j].x, v[j].y), fmaxf(v[j].z, v[j].w)));
#pragma unroll
    for (int off = 16; off > 0; off >>= 1)
        m = fmaxf(m, __shfl_xor_sync(0xffffffffu, m, off));
    if (lane == 0) smax[warp] = m;
    __syncthreads();
    float mm = smax[0];
#pragma unroll
    for (int w = 1; w < 8; w++) mm = fmaxf(mm, smax[w]);

    float tau = mm - 1.0f;

#pragma unroll 1
    for (int it = 0; it < 32; it++) {
        const int p = it & 1;
        float a = 0.f, q = 0.f;
#pragma unroll
        for (int j = 0; j < 8; j++) {
            float d;
            d = fmaxf(v[j].x - tau, 0.f); a += d; q = fmaf(d, d, q);
            d = fmaxf(v[j].y - tau, 0.f); a += d; q = fmaf(d, d, q);
            d = fmaxf(v[j].z - tau, 0.f); a += d; q = fmaf(d, d, q);
            d = fmaxf(v[j].w - tau, 0.f); a += d; q = fmaf(d, d, q);
        }
#pragma unroll
        for (int off = 16; off > 0; off >>= 1) {
            a += __shfl_xor_sync(0xffffffffu, a, off);
            q += __shfl_xor_sync(0xffffffffu, q, off);
        }
        if (lane == 0) { s1[p][warp] = a; s2[p][warp] = q; }
        __syncthreads();
        float S1 = 0.f, S2 = 0.f;
#pragma unroll
        for (int w = 0; w < 8; w++) { S1 += s1[p][w]; S2 += s2[p][w]; }
        if (S1 <= 0.f) break;
        float gg = sqrtf(S2);
        float dt = (S2 - gg) / S1;    // Newton step on g(tau)-1
        tau += dt;
        if (fabsf(dt) < 1e-7f) break;
    }

#pragma unroll
    for (int j = 0; j < 8; j++) {
        float4 o;
        float d;
        d = fmaxf(v[j].x - tau, 0.f); o.x = d * d;
        d = fmaxf(v[j].y - tau, 0.f); o.y = d * d;
        d = fmaxf(v[j].z - tau, 0.f); o.z = d * d;
        d = fmaxf(v[j].w - tau, 0.f); o.w = d * d;
        row[tid + 256 * j] = o;
    }
}

// ---------------------------------------------------------------------------
extern "C" void kernel_launch(void* const* d_in, const int* in_sizes, int n_in,
                              void* d_out, int out_size)
{
    const float* edge_repr = (const float*)d_in[0];
    const float* sub_repr  = (const float*)d_in[1];
    const float* W_sub     = (const float*)d_in[2];
    const float* b_sub     = (const float*)d_in[3];
    const float* W_edge    = (const float*)d_in[4];
    const float* b_edge    = (const float*)d_in[5];
    const float* log_scale = (const float*)d_in[6];
    float* out = (float*)d_out;

    cudaFuncSetAttribute(scores_mma_kernel,
                         cudaFuncAttributeMaxDynamicSharedMemorySize, SMEM_SC);

    proj_kernel<<<NS / 16, 256>>>(sub_repr,  W_sub,  b_sub,  0);
    proj_kernel<<<NE / 16, 256>>>(edge_repr, W_edge, b_edge, 1);

    dim3 grid(NE / 128, NS / 128);
    scores_mma_kernel<<<grid, 256, SMEM_SC>>>(log_scale, out);

    entmax_kernel<<<NS, 256>>>(out);
}

// round 6
// speedup vs baseline: 1.8168x; 1.2762x over previous
#include <cuda_runtime.h>
#include <cuda_fp16.h>
#include <cstdint>
#include <math.h>

#define NS 8192
#define NE 8192
#define HH 512
#define PP 64
#define KC 128              // fp16 concat K = [hi(64) | lo(64)]

// fp16 split operands: [N, 128] row-major (256B per row).
__device__ __half g_sub_cat[(size_t)NS * KC];
__device__ __half g_edge_cat[(size_t)NE * KC];

__device__ __forceinline__ uint32_t smem_u32(const void* p) {
    uint32_t a;
    asm("{ .reg .u64 t; cvta.to.shared.u64 t, %1; cvt.u32.u64 %0, t; }" : "=r"(a) : "l"(p));
    return a;
}
__device__ __forceinline__ void ldmx4(uint32_t* r, uint32_t addr) {
    asm volatile("ldmatrix.sync.aligned.m8n8.x4.shared.b16 {%0,%1,%2,%3}, [%4];"
                 : "=r"(r[0]), "=r"(r[1]), "=r"(r[2]), "=r"(r[3]) : "r"(addr));
}
// f16 x f16 -> f32 accum
__device__ __forceinline__ void mma_f32(float* d, const uint32_t* a, const uint32_t* b) {
    asm volatile(
        "mma.sync.aligned.m16n8k16.row.col.f32.f16.f16.f32 "
        "{%0,%1,%2,%3}, {%4,%5,%6,%7}, {%8,%9}, {%0,%1,%2,%3};"
        : "+f"(d[0]), "+f"(d[1]), "+f"(d[2]), "+f"(d[3])
        : "r"(a[0]), "r"(a[1]), "r"(a[2]), "r"(a[3]), "r"(b[0]), "r"(b[1]));
}
// f16 x f16 -> f16 accum (corrections only; tiny magnitudes)
__device__ __forceinline__ void mma_f16(uint32_t* d, const uint32_t* a, const uint32_t* b) {
    asm volatile(
        "mma.sync.aligned.m16n8k16.row.col.f16.f16.f16.f16 "
        "{%0,%1}, {%2,%3,%4,%5}, {%6,%7}, {%0,%1};"
        : "+r"(d[0]), "+r"(d[1])
        : "r"(a[0]), "r"(a[1]), "r"(a[2]), "r"(a[3]), "r"(b[0]), "r"(b[1]));
}
__device__ __forceinline__ void cpa16(uint32_t s, const void* g) {
    asm volatile("cp.async.cg.shared.global [%0], [%1], 16;" :: "r"(s), "l"(g) : "memory");
}

// ---------------------------------------------------------------------------
// proj: out = l2_normalize(X @ W^T + b) -> fp16 hi/lo [N,128].
// One launch handles both projections (blockIdx.y: 0=sub, 1=edge).
// CTA: 64 rows x 64 cols, K=512 in 8 chunks of 64, transposed smem.
// ---------------------------------------------------------------------------
__global__ __launch_bounds__(256) void proj_kernel(const float* __restrict__ Xs_in,
                                                   const float* __restrict__ Xe_in,
                                                   const float* __restrict__ Ws_in,
                                                   const float* __restrict__ bs_in,
                                                   const float* __restrict__ We_in,
                                                   const float* __restrict__ be_in)
{
    __shared__ float Xs[64 * 64];   // [k][row]
    __shared__ float Ws[64 * 64];   // [k][col]

    const int which = blockIdx.y;
    const float4* X4 = reinterpret_cast<const float4*>(which ? Xe_in : Xs_in);
    const float4* W4 = reinterpret_cast<const float4*>(which ? We_in : Ws_in);
    const float*  bb = which ? be_in : bs_in;
    __half* out = which ? g_edge_cat : g_sub_cat;

    const int tid = threadIdx.x;
    const int tx = tid & 15;
    const int ty = tid >> 4;
    const int rbase = blockIdx.x * 64;

    float acc[4][4];
#pragma unroll
    for (int i = 0; i < 4; i++)
#pragma unroll
        for (int j = 0; j < 4; j++) acc[i][j] = 0.f;

#pragma unroll 1
    for (int kc = 0; kc < 8; kc++) {
        if (kc) __syncthreads();
#pragma unroll
        for (int it = 0; it < 4; it++) {
            int t = tid + it * 256;      // 0..1023
            int row = t & 63;
            int q   = t >> 6;            // 0..15 (float4 within 64-float chunk)
            float4 vx = X4[(size_t)(rbase + row) * 128 + kc * 16 + q];
            Xs[(4 * q + 0) * 64 + row] = vx.x; Xs[(4 * q + 1) * 64 + row] = vx.y;
            Xs[(4 * q + 2) * 64 + row] = vx.z; Xs[(4 * q + 3) * 64 + row] = vx.w;
            float4 vw = W4[(size_t)row * 128 + kc * 16 + q];
            Ws[(4 * q + 0) * 64 + row] = vw.x; Ws[(4 * q + 1) * 64 + row] = vw.y;
            Ws[(4 * q + 2) * 64 + row] = vw.z; Ws[(4 * q + 3) * 64 + row] = vw.w;
        }
        __syncthreads();
#pragma unroll
        for (int k = 0; k < 64; k++) {
            float4 a  = *reinterpret_cast<const float4*>(&Xs[k * 64 + ty * 4]);
            float4 bv = *reinterpret_cast<const float4*>(&Ws[k * 64 + tx * 4]);
            const float av[4] = {a.x, a.y, a.z, a.w};
            const float bw[4] = {bv.x, bv.y, bv.z, bv.w};
#pragma unroll
            for (int i = 0; i < 4; i++)
#pragma unroll
                for (int j = 0; j < 4; j++)
                    acc[i][j] = fmaf(av[i], bw[j], acc[i][j]);
        }
    }

    // bias
#pragma unroll
    for (int j = 0; j < 4; j++) {
        float bj = bb[tx * 4 + j];
#pragma unroll
        for (int i = 0; i < 4; i++) acc[i][j] += bj;
    }

    // row L2 norms (reduce across 16 tx threads; tx bits = lane bits 0..3)
#pragma unroll
    for (int i = 0; i < 4; i++) {
        float rs = acc[i][0] * acc[i][0] + acc[i][1] * acc[i][1]
                 + acc[i][2] * acc[i][2] + acc[i][3] * acc[i][3];
#pragma unroll
        for (int off = 1; off < 16; off <<= 1)
            rs += __shfl_xor_sync(0xffffffffu, rs, off);
        float inv = 1.0f / fmaxf(sqrtf(rs), 1e-12f);

        int row = rbase + ty * 4 + i;
        __half h[4], l[4];
#pragma unroll
        for (int j = 0; j < 4; j++) {
            float v = acc[i][j] * inv;
            h[j] = __float2half(v);
            l[j] = __float2half(v - __half2float(h[j]));
        }
        uint2 hp, lp;
        hp.x = ((uint32_t)__half_as_ushort(h[1]) << 16) | __half_as_ushort(h[0]);
        hp.y = ((uint32_t)__half_as_ushort(h[3]) << 16) | __half_as_ushort(h[2]);
        lp.x = ((uint32_t)__half_as_ushort(l[1]) << 16) | __half_as_ushort(l[0]);
        lp.y = ((uint32_t)__half_as_ushort(l[3]) << 16) | __half_as_ushort(l[2]);
        *reinterpret_cast<uint2*>(&out[(size_t)row * KC + tx * 4])      = hp;
        *reinterpret_cast<uint2*>(&out[(size_t)row * KC + 64 + tx * 4]) = lp;
    }
}

// ---------------------------------------------------------------------------
// scores GEMM: 128x64 tile/CTA. K=128 fp16 [hi|lo] loaded once (48KB smem).
// hi*hi -> f32 accum;  hi*lo + lo*hi -> f16 accum (magnitude ~2^-12).
// ---------------------------------------------------------------------------
__global__ __launch_bounds__(256, 2) void scores_mma_kernel(const float* __restrict__ log_scale,
                                                            float* __restrict__ out)
{
    __shared__ char smem[49152];
    const uint32_t sA = smem_u32(smem);     // 32KB: 256 swizzle-rows of 128B
    const uint32_t sB = sA + 32768;         // 16KB: 128 swizzle-rows

    const int tid  = threadIdx.x;
    const int wid  = tid >> 5;
    const int lane = tid & 31;
    const int wm = wid & 3;        // 4 warps along M (32 each)
    const int wn = wid >> 2;       // 2 warps along N (32 each)
    const int brow = blockIdx.y * 128;
    const int bcol = blockIdx.x * 64;

    const char* gA = reinterpret_cast<const char*>(g_sub_cat);
    const char* gB = reinterpret_cast<const char*>(g_edge_cat);

    // A: 128 rows x 256B = 2048 quads; sr = chunk*128 + row
#pragma unroll
    for (int it = 0; it < 8; it++) {
        int qi = tid + it * 256;
        int sr = qi >> 3, lq = qi & 7;
        int r = sr & 127, c = sr >> 7;
        cpa16(sA + sr * 128 + ((lq ^ (sr & 7)) << 4),
              gA + (size_t)(brow + r) * 256 + c * 128 + lq * 16);
    }
    // B: 64 rows x 256B = 1024 quads; sr = chunk*64 + row
#pragma unroll
    for (int it = 0; it < 4; it++) {
        int qi = tid + it * 256;
        int sr = qi >> 3, lq = qi & 7;
        int r = sr & 63, c = sr >> 6;
        cpa16(sB + sr * 128 + ((lq ^ (sr & 7)) << 4),
              gB + (size_t)(bcol + r) * 256 + c * 128 + lq * 16);
    }
    asm volatile("cp.async.commit_group;" ::: "memory");
    asm volatile("cp.async.wait_group 0;" ::: "memory");
    __syncthreads();

    float    accf[2][4][4];
    uint32_t acch[2][4][2];
#pragma unroll
    for (int mt = 0; mt < 2; mt++)
#pragma unroll
        for (int nt = 0; nt < 4; nt++) {
#pragma unroll
            for (int q = 0; q < 4; q++) accf[mt][nt][q] = 0.f;
            acch[mt][nt][0] = 0u; acch[mt][nt][1] = 0u;
        }

    const int g  = lane >> 3;
    const int rl = lane & 7;
    const int gl = g & 1;
    const int gh = g >> 1;

    uint32_t aOff[2][2];   // [chunk][mt]
#pragma unroll
    for (int ca = 0; ca < 2; ca++)
#pragma unroll
        for (int mt = 0; mt < 2; mt++)
            aOff[ca][mt] = sA + (uint32_t)(ca * 128 + wm * 32 + mt * 16 + rl + gl * 8) * 128u;
    uint32_t bOff[2][2];   // [chunk][pn]
#pragma unroll
    for (int cb = 0; cb < 2; cb++)
#pragma unroll
        for (int pn = 0; pn < 2; pn++)
            bOff[cb][pn] = sB + (uint32_t)(cb * 64 + wn * 32 + pn * 16 + rl + gh * 8) * 128u;

#pragma unroll
    for (int s = 0; s < 4; s++) {
        const uint32_t ca_col = (uint32_t)(((2 * s + gh) ^ rl) << 4);
        const uint32_t cb_col = (uint32_t)(((2 * s + gl) ^ rl) << 4);
        uint32_t a0[2][4], a1[2][4], b0[2][4], b1[2][4];
#pragma unroll
        for (int mt = 0; mt < 2; mt++) {
            ldmx4(a0[mt], aOff[0][mt] + ca_col);   // hi
            ldmx4(a1[mt], aOff[1][mt] + ca_col);   // lo
        }
#pragma unroll
        for (int pn = 0; pn < 2; pn++) {
            ldmx4(b0[pn], bOff[0][pn] + cb_col);   // hi
            ldmx4(b1[pn], bOff[1][pn] + cb_col);   // lo
        }
#pragma unroll
        for (int mt = 0; mt < 2; mt++)
#pragma unroll
            for (int pn = 0; pn < 2; pn++) {
                // hi * hi  (f32 accum)
                mma_f32(accf[mt][2 * pn],     a0[mt], &b0[pn][0]);
                mma_f32(accf[mt][2 * pn + 1], a0[mt], &b0[pn][2]);
                // hi * lo  (f16 accum)
                mma_f16(acch[mt][2 * pn],     a0[mt], &b1[pn][0]);
                mma_f16(acch[mt][2 * pn + 1], a0[mt], &b1[pn][2]);
                // lo * hi  (f16 accum)
                mma_f16(acch[mt][2 * pn],     a1[mt], &b0[pn][0]);
                mma_f16(acch[mt][2 * pn + 1], a1[mt], &b0[pn][2]);
            }
    }

    const float zs = 0.5f * fminf(fmaxf(expf(*log_scale), 0.5f), 20.0f);

    const int r0 = brow + wm * 32 + (lane >> 2);
    const int c0 = bcol + wn * 32 + 2 * (lane & 3);
#pragma unroll
    for (int mt = 0; mt < 2; mt++)
#pragma unroll
        for (int nt = 0; nt < 4; nt++) {
            float2 c01 = __half22float2(*reinterpret_cast<__half2*>(&acch[mt][nt][0]));
            float2 c23 = __half22float2(*reinterpret_cast<__half2*>(&acch[mt][nt][1]));
            float* p0 = out + (size_t)(r0 + mt * 16) * NE + c0 + nt * 8;
            float* p1 = p0 + 8 * NE;
            *reinterpret_cast<float2*>(p0) =
                make_float2((accf[mt][nt][0] + c01.x) * zs, (accf[mt][nt][1] + c01.y) * zs);
            *reinterpret_cast<float2*>(p1) =
                make_float2((accf[mt][nt][2] + c23.x) * zs, (accf[mt][nt][3] + c23.y) * zs);
        }
}

// ---------------------------------------------------------------------------
// entmax-1.5 per row, in place. Newton on g(tau)=sqrt(sum relu(z-tau)^2)=1
// from tau0 = zmax-1 (monotone increasing). Since tau only increases,
// elements <= zmax-1 never contribute: compact survivors to a smem pool once,
// then iterate over the (much smaller) pool.
// ---------------------------------------------------------------------------
__global__ __launch_bounds__(256) void entmax_kernel(float* __restrict__ out)
{
    __shared__ float pool[8192];
    __shared__ float red1[2][8], red2[2][8], smax[8];
    __shared__ int s_cnt;

    const int tid  = threadIdx.x;
    const int lane = tid & 31;
    const int warp = tid >> 5;
    float4* row = reinterpret_cast<float4*>(out + (size_t)blockIdx.x * NE);

    float4 v[8];
#pragma unroll
    for (int j = 0; j < 8; j++) v[j] = row[tid + 256 * j];

    if (tid == 0) s_cnt = 0;

    // row max
    float m = -3.4e38f;
#pragma unroll
    for (int j = 0; j < 8; j++)
        m = fmaxf(m, fmaxf(fmaxf(v[j].x, v[j].y), fmaxf(v[j].z, v[j].w)));
#pragma unroll
    for (int off = 16; off > 0; off >>= 1)
        m = fmaxf(m, __shfl_xor_sync(0xffffffffu, m, off));
    if (lane == 0) smax[warp] = m;
    __syncthreads();
    float mm = smax[0];
#pragma unroll
    for (int w = 1; w < 8; w++) mm = fmaxf(mm, smax[w]);
    const float thr = mm - 1.0f;

    // compact candidates (z > thr) into pool
    int nc = 0;
#pragma unroll
    for (int j = 0; j < 8; j++) {
        nc += (v[j].x > thr) + (v[j].y > thr) + (v[j].z > thr) + (v[j].w > thr);
    }
    int pref = nc;
#pragma unroll
    for (int off = 1; off < 32; off <<= 1) {
        int t = __shfl_up_sync(0xffffffffu, pref, off);
        if (lane >= off) pref += t;
    }
    int wtot = __shfl_sync(0xffffffffu, pref, 31);
    int wbase = 0;
    if (lane == 31) wbase = atomicAdd(&s_cnt, wtot);
    wbase = __shfl_sync(0xffffffffu, wbase, 31);
    int idx = wbase + pref - nc;
#pragma unroll
    for (int j = 0; j < 8; j++) {
        if (v[j].x > thr) pool[idx++] = v[j].x;
        if (v[j].y > thr) pool[idx++] = v[j].y;
        if (v[j].z > thr) pool[idx++] = v[j].z;
        if (v[j].w > thr) pool[idx++] = v[j].w;
    }
    __syncthreads();
    const int n = s_cnt;

    float tau = thr;
#pragma unroll 1
    for (int it = 0; it < 40; it++) {
        const int p = it & 1;
        float a = 0.f, q = 0.f;
        for (int i = tid; i < n; i += 256) {
            float d = fmaxf(pool[i] - tau, 0.f);
            a += d; q = fmaf(d, d, q);
        }
#pragma unroll
        for (int off = 16; off > 0; off >>= 1) {
            a += __shfl_xor_sync(0xffffffffu, a, off);
            q += __shfl_xor_sync(0xffffffffu, q, off);
        }
        if (lane == 0) { red1[p][warp] = a; red2[p][warp] = q; }
        __syncthreads();
        float S1 = 0.f, S2 = 0.f;
#pragma unroll
        for (int w = 0; w < 8; w++) { S1 += red1[p][w]; S2 += red2[p][w]; }
        if (S1 <= 0.f) break;
        float dt = (S2 - sqrtf(S2)) / S1;    // Newton step on g(tau)-1
        tau += dt;
        if (fabsf(dt) < 1e-7f) break;
    }

#pragma unroll
    for (int j = 0; j < 8; j++) {
        float4 o;
        float d;
        d = fmaxf(v[j].x - tau, 0.f); o.x = d * d;
        d = fmaxf(v[j].y - tau, 0.f); o.y = d * d;
        d = fmaxf(v[j].z - tau, 0.f); o.z = d * d;
        d = fmaxf(v[j].w - tau, 0.f); o.w = d * d;
        row[tid + 256 * j] = o;
    }
}

// ---------------------------------------------------------------------------
extern "C" void kernel_launch(void* const* d_in, const int* in_sizes, int n_in,
                              void* d_out, int out_size)
{
    const float* edge_repr = (const float*)d_in[0];
    const float* sub_repr  = (const float*)d_in[1];
    const float* W_sub     = (const float*)d_in[2];
    const float* b_sub     = (const float*)d_in[3];
    const float* W_edge    = (const float*)d_in[4];
    const float* b_edge    = (const float*)d_in[5];
    const float* log_scale = (const float*)d_in[6];
    float* out = (float*)d_out;

    proj_kernel<<<dim3(NS / 64, 2), 256>>>(sub_repr, edge_repr,
                                           W_sub, b_sub, W_edge, b_edge);

    dim3 grid(NE / 64, NS / 128);
    scores_mma_kernel<<<grid, 256>>>(log_scale, out);

    entmax_kernel<<<NS, 256>>>(out);
}